// round 6
// baseline (speedup 1.0000x reference)
#include <cuda_runtime.h>
#include <cstdint>

#define DTW_INF 99999.0f

// Bench size: N = M = 6144.
constexpr int MAXN = 6144;
constexpr int MAXM = 6144;
constexpr int PITCH = (MAXM + 4 + 3) & ~3;     // 6148, multiple of 4

// Diagonal-major scratch with +3 shift: cell (i,j) at g_buf[(i+j)*PITCH + j+3].
__device__ float g_buf[(size_t)(MAXN + MAXM + 2) * PITCH + 16];

constexpr int SW  = 128;    // strip width (columns per warp)
constexpr int W   = 4;      // columns per lane
constexpr int B   = 32;     // steps per synchronization chunk
constexpr int WPB = 4;      // warps per block (1 per SMSP)
constexpr int MAXSTRIPS = 64;
constexpr int HALO_PITCH = MAXN + 64;
constexpr int N4MAX = (MAXN + 3) / 4 + 8;

// halo[s][i] = v(i, cs-1) : left-boundary column for strip s (produced by s-1).
__device__ float g_halo[MAXSTRIPS * HALO_PITCH];
// g_prog[s*32] = highest row i such that halo[s][0..i] is published.
__device__ volatile int g_prog[MAXSTRIPS * 32];

__device__ __forceinline__ size_t gidx(int d, int j) {
    return (size_t)d * PITCH + (j + 3);
}

// ---------------------------------------------------------------------------
// Init: g_buf boundaries, halo[0] prefill, halo[s][0], progress flags.
// ---------------------------------------------------------------------------
__global__ void dtw_init(int N, int M, int nstrips)
{
    const int stride = gridDim.x * blockDim.x;
    const int idx = blockIdx.x * blockDim.x + threadIdx.x;
    for (int j = idx; j <= M; j += stride)
        g_buf[gidx(j, j)] = (j == 0) ? 0.0f : DTW_INF;
    for (int i = idx + 1; i <= N; i += stride)
        g_buf[gidx(i, 0)] = DTW_INF;
    for (int i = idx; i <= N; i += stride)
        g_halo[i] = (i == 0) ? 0.0f : DTW_INF;        // strip 0 left halo (col 0)
    for (int t = idx; t < nstrips; t += stride) {
        g_prog[t * 32] = (t == 0) ? N : 0;
        if (t >= 1) g_halo[t * HALO_PITCH] = DTW_INF; // v(0, cs-1)
    }
}

// ---------------------------------------------------------------------------
// Fast (steady-state) step: no predicates, ping-pong buffers, float4 store.
// a = diag d-1 values, b = diag d-2 (overwritten with new diag d).
// xw is residue-indexed: xw[r] holds x value with index == r (mod 4).
// ---------------------------------------------------------------------------
template<int E>
__device__ __forceinline__ void fast_step(
    float (&a)[W], float (&b)[W], float (&xw)[W], const float (&yv)[W],
    float xn, float nh, float& hl, int lane,
    float*& pg, float* hdst, int& i31)
{
    float nl = __shfl_up_sync(0xffffffffu, a[3], 1);   // v(i0,   j0-1)
    float np = __shfl_up_sync(0xffffffffu, b[3], 1);   // v(i0-1, j0-1)
    if (lane == 0) { nl = nh; np = hl; }
    hl = nh;
    xw[E & 3] = xn;
    float dpr = np, lft = nl;
#pragma unroll
    for (int c = 0; c < W; ++c) {
        float top = a[c], old = b[c];
        float dd = xw[(E - c) & 3] - yv[c];
        b[c] = fmaf(dd, dd, fminf(fminf(top, lft), dpr));
        dpr = old; lft = top;
    }
    *reinterpret_cast<float4*>(pg) = make_float4(b[0], b[1], b[2], b[3]);
    pg += PITCH;
    if (lane == 31) hdst[i31] = b[3];
    ++i31;
}

// ---------------------------------------------------------------------------
// Persistent pipelined wavefront. One warp per 128-column strip.
// ---------------------------------------------------------------------------
__global__ __launch_bounds__(WPB * 32)
void dtw_wave(const float* __restrict__ x, const float* __restrict__ y,
              int N, int M, int nstrips)
{
    __shared__ float xs[4][N4MAX];          // x deinterleaved: xs[r][k]=x[4k+r]
    __shared__ float hbuf[WPB][B + 4];      // per-warp halo chunk

    const int tid = threadIdx.x;
    const int lane = tid & 31;
    const int w = tid >> 5;
    const int N4 = (N + 3) >> 2;

    for (int k = tid; k < N; k += WPB * 32)
        xs[k & 3][k >> 2] = x[k];
    __syncthreads();

    const int s = blockIdx.x * WPB + w;
    if (s >= nstrips) return;

    const int cs = 1 + SW * s;              // first column of strip
    const int j0 = cs + W * lane;           // first column of this lane
    const bool fullstrip = (cs + SW - 1 <= M);

    float yv[W];
#pragma unroll
    for (int c = 0; c < W; ++c)
        yv[c] = (j0 + c <= M) ? y[j0 + c - 1] : 0.0f;

    float cur[W], oth[W], xw[W];
#pragma unroll
    for (int c = 0; c < W; ++c) { cur[c] = DTW_INF; oth[c] = DTW_INF; xw[c] = 0.0f; }

    const float* hsrc = g_halo + s * HALO_PITCH;
    float* hdst = g_halo + (s + 1) * HALO_PITCH;
    const bool has_prod = (s > 0);
    const bool has_cons = (s + 1 < nstrips) && fullstrip;

    const int d_lo = cs + 1;
    const int d_hi = cs + SW - 1 + N;
    bool was_steady = false;

    for (int d0 = d_lo; d0 <= d_hi; d0 += B) {
        const int dend = (d0 + B - 1 < d_hi) ? (d0 + B - 1) : d_hi;

        // --- acquire producer progress ---
        if (has_prod) {
            int i_need = dend - cs; if (i_need > N) i_need = N;
            if (lane == 0) {
                while (g_prog[s * 32] < i_need) { }
                __threadfence();
            }
        }
        __syncwarp();   // also protects hbuf reuse across chunks

        // --- stage halo rows [d0-cs-1 .. d0-cs-1+B] (L1-bypassed) ---
        {
            const int i_base = d0 - cs - 1;
            int ii = i_base + lane; ii = ii < 0 ? 0 : (ii > N ? N : ii);
            hbuf[w][lane] = __ldcg(&hsrc[ii]);
            if (lane == 0) {
                int i2 = i_base + B; i2 = i2 < 0 ? 0 : (i2 > N ? N : i2);
                hbuf[w][B] = __ldcg(&hsrc[i2]);
            }
            __syncwarp();
        }

        const bool steady = fullstrip && (d0 >= cs + SW) && (dend <= cs + N)
                            && (dend == d0 + B - 1);
        if (steady != was_steady) {
            // translate xw between shift-indexed and residue-indexed: reverse.
            float t0 = xw[0], t1 = xw[1];
            xw[0] = xw[3]; xw[3] = t0; xw[1] = xw[2]; xw[2] = t1;
            was_steady = steady;
        }

        if (steady) {
            const int q0 = d0 - cs - 1;                 // multiple of 32
            const int kb = (q0 >> 2) - lane;
            float* pg = g_buf + gidx(d0, j0);
            float hl = hbuf[w][0];
            int i31 = q0 - 126;                         // lane31 c=3 row at step 0
#pragma unroll 2
            for (int eb = 0; eb < B; eb += 4) {
                const int kk = kb + (eb >> 2);
                const float x0 = xs[0][kk], x1 = xs[1][kk];
                const float x2 = xs[2][kk], x3 = xs[3][kk];
                fast_step<0>(cur, oth, xw, yv, x0, hbuf[w][eb + 1], hl, lane, pg, hdst, i31);
                fast_step<1>(oth, cur, xw, yv, x1, hbuf[w][eb + 2], hl, lane, pg, hdst, i31);
                fast_step<2>(cur, oth, xw, yv, x2, hbuf[w][eb + 3], hl, lane, pg, hdst, i31);
                fast_step<3>(oth, cur, xw, yv, x3, hbuf[w][eb + 4], hl, lane, pg, hdst, i31);
            }
        } else {
            float* pg = g_buf + gidx(d0, j0);
            for (int d = d0; d <= dend; ++d) {
                const int e = d - d0;
                const int q = d - cs - 1;
                int kk = (q >> 2) - lane;
                kk = kk < 0 ? 0 : (kk >= N4 ? N4 - 1 : kk);
                const float xn = xs[q & 3][kk];
                float nl = __shfl_up_sync(0xffffffffu, cur[3], 1);
                float np = __shfl_up_sync(0xffffffffu, oth[3], 1);
                if (lane == 0) { nl = hbuf[w][e + 1]; np = hbuf[w][e]; }
                xw[3] = xw[2]; xw[2] = xw[1]; xw[1] = xw[0]; xw[0] = xn;
                float dpr = np, lft = nl;
#pragma unroll
                for (int c = 0; c < W; ++c) {
                    const int i = d - j0 - c;
                    float top = cur[c], old = oth[c];
                    float dd = xw[c] - yv[c];
                    float v = fmaf(dd, dd, fminf(fminf(top, lft), dpr));
                    oth[c] = top;
                    cur[c] = (i >= 1) ? v : DTW_INF;
                    if (i >= 1 && i <= N && (j0 + c) <= M) pg[c] = v;
                    dpr = old; lft = top;
                }
                pg += PITCH;
                if (lane == 31) {
                    const int i31 = d - j0 - 3;
                    if (has_cons && i31 >= 1 && i31 <= N) hdst[i31] = cur[3];
                }
            }
        }

        // --- release progress to consumer ---
        if (has_cons && lane == 31) {
            int ip = dend - cs - (SW - 1);
            if (ip > 0) {
                if (ip > N) ip = N;
                __threadfence();
                g_prog[(s + 1) * 32] = ip;
            }
        }
    }
}

// ---------------------------------------------------------------------------
// De-skew + sqrt: out[i][j] = sqrt(g_buf[gidx(i+j, j)]).
// ---------------------------------------------------------------------------
constexpr int TR = 128;
constexpr int TC = 32;

__global__ __launch_bounds__(256)
void dtw_deskew(float* __restrict__ out, int N, int M)
{
    __shared__ float sh[TR + TC - 1][TC];
    const int i0 = blockIdx.y * TR;
    const int j0 = blockIdx.x * TC;
    const int d0 = i0 + j0;
    const int pitch_out = M + 1;

    for (int k = threadIdx.x; k < (TR + TC - 1) * TC; k += 256) {
        int dl = k >> 5;
        int jl = k & 31;
        int dg = d0 + dl;
        int jg = j0 + jl;
        float v = 0.0f;
        if (dg <= N + M && jg <= M)
            v = g_buf[gidx(dg, jg)];
        sh[dl][jl] = v;
    }
    __syncthreads();

    for (int k = threadIdx.x; k < TR * TC; k += 256) {
        int ii = k >> 5;
        int jl = k & 31;
        int ig = i0 + ii;
        int jg = j0 + jl;
        if (ig <= N && jg <= M)
            out[(size_t)ig * pitch_out + jg] = sqrtf(sh[ii + jl][jl]);
    }
}

// ---------------------------------------------------------------------------
extern "C" void kernel_launch(void* const* d_in, const int* in_sizes, int n_in,
                              void* d_out, int out_size)
{
    const float* x = (const float*)d_in[0];
    const float* y = (const float*)d_in[1];
    float* out = (float*)d_out;
    const int N = in_sizes[0];
    const int M = in_sizes[1];

    const int nstrips = (M + SW - 1) / SW;            // 48 for M=6144
    dtw_init<<<64, 256>>>(N, M, nstrips);

    const int nblocks = (nstrips + WPB - 1) / WPB;    // 12 blocks, all resident
    dtw_wave<<<nblocks, WPB * 32>>>(x, y, N, M, nstrips);

    dim3 grid((M + 1 + TC - 1) / TC, (N + 1 + TR - 1) / TR);
    dtw_deskew<<<grid, 256>>>(out, N, M);
}

// round 7
// speedup vs baseline: 1.0038x; 1.0038x over previous
#include <cuda_runtime.h>
#include <cstdint>

#define DTW_INF 99999.0f

// Bench size: N = M = 6144.
constexpr int MAXN = 6144;
constexpr int MAXM = 6144;
constexpr int PITCH = (MAXM + 4 + 3) & ~3;     // 6148, multiple of 4

// Diagonal-major scratch with +3 shift: cell (i,j) at g_buf[(i+j)*PITCH + j+3].
__device__ float g_buf[(size_t)(MAXN + MAXM + 2) * PITCH + 16];

constexpr int SW  = 128;    // strip width (columns per warp)
constexpr int W   = 4;      // columns per lane
constexpr int B   = 32;     // steps per synchronization chunk
constexpr int WPB = 4;      // warps per block (1 per SMSP)
constexpr int MAXSTRIPS = 64;
constexpr int HALO_PITCH = MAXN + 64;
constexpr int N4MAX = (MAXN + 3) / 4 + 8;

// halo[s][i] = v(i, cs-1) : left-boundary column for strip s (produced by s-1).
__device__ float g_halo[MAXSTRIPS * HALO_PITCH];
// g_prog[s*32] = highest row i such that halo[s][0..i] is published.
__device__ volatile int g_prog[MAXSTRIPS * 32];

__device__ __forceinline__ size_t gidx(int d, int j) {
    return (size_t)d * PITCH + (j + 3);
}

// ---------------------------------------------------------------------------
// Init: g_buf boundaries, halo[0] prefill, halo[s][0], progress flags.
// ---------------------------------------------------------------------------
__global__ void dtw_init(int N, int M, int nstrips)
{
    const int stride = gridDim.x * blockDim.x;
    const int idx = blockIdx.x * blockDim.x + threadIdx.x;
    for (int j = idx; j <= M; j += stride)
        g_buf[gidx(j, j)] = (j == 0) ? 0.0f : DTW_INF;
    for (int i = idx + 1; i <= N; i += stride)
        g_buf[gidx(i, 0)] = DTW_INF;
    for (int i = idx; i <= N; i += stride)
        g_halo[i] = (i == 0) ? 0.0f : DTW_INF;        // strip 0 left halo (col 0)
    for (int t = idx; t < nstrips; t += stride) {
        g_prog[t * 32] = (t == 0) ? N : 0;
        if (t >= 1) g_halo[t * HALO_PITCH] = DTW_INF; // v(0, cs-1)
    }
}

// ---------------------------------------------------------------------------
// Fast (steady-state) step: no predicates, ping-pong buffers, float4 store.
// a = diag d-1 values, b = diag d-2 (overwritten with new diag d).
// xw is residue-indexed: xw[r] holds x value with index == r (mod 4).
// ---------------------------------------------------------------------------
template<int E>
__device__ __forceinline__ void fast_step(
    float (&a)[W], float (&b)[W], float (&xw)[W], const float (&yv)[W],
    float xn, float nh, float& hl, int lane,
    float*& pg, float* hdst, int& i31)
{
    float nl = __shfl_up_sync(0xffffffffu, a[3], 1);   // v(i0,   j0-1)
    float np = __shfl_up_sync(0xffffffffu, b[3], 1);   // v(i0-1, j0-1)
    if (lane == 0) { nl = nh; np = hl; }
    hl = nh;
    xw[E & 3] = xn;
    float dpr = np, lft = nl;
#pragma unroll
    for (int c = 0; c < W; ++c) {
        float top = a[c], old = b[c];
        float dd = xw[(E - c) & 3] - yv[c];
        b[c] = fmaf(dd, dd, fminf(fminf(top, lft), dpr));
        dpr = old; lft = top;
    }
    *reinterpret_cast<float4*>(pg) = make_float4(b[0], b[1], b[2], b[3]);
    pg += PITCH;
    if (lane == 31) hdst[i31] = b[3];
    ++i31;
}

// ---------------------------------------------------------------------------
// Persistent pipelined wavefront. One warp per 128-column strip.
// ---------------------------------------------------------------------------
__global__ __launch_bounds__(WPB * 32)
void dtw_wave(const float* __restrict__ x, const float* __restrict__ y,
              int N, int M, int nstrips)
{
    __shared__ float xs[4][N4MAX];          // x deinterleaved: xs[r][k]=x[4k+r]
    __shared__ float hbuf[WPB][B + 4];      // per-warp halo chunk

    const int tid = threadIdx.x;
    const int lane = tid & 31;
    const int w = tid >> 5;
    const int N4 = (N + 3) >> 2;

    for (int k = tid; k < N; k += WPB * 32)
        xs[k & 3][k >> 2] = x[k];
    __syncthreads();

    const int s = blockIdx.x * WPB + w;
    if (s >= nstrips) return;

    const int cs = 1 + SW * s;              // first column of strip
    const int j0 = cs + W * lane;           // first column of this lane
    const bool fullstrip = (cs + SW - 1 <= M);

    float yv[W];
#pragma unroll
    for (int c = 0; c < W; ++c)
        yv[c] = (j0 + c <= M) ? y[j0 + c - 1] : 0.0f;

    float cur[W], oth[W], xw[W];
#pragma unroll
    for (int c = 0; c < W; ++c) { cur[c] = DTW_INF; oth[c] = DTW_INF; xw[c] = 0.0f; }

    const float* hsrc = g_halo + s * HALO_PITCH;
    float* hdst = g_halo + (s + 1) * HALO_PITCH;
    const bool has_prod = (s > 0);
    const bool has_cons = (s + 1 < nstrips) && fullstrip;

    const int d_lo = cs + 1;
    const int d_hi = cs + SW - 1 + N;
    bool was_steady = false;

    for (int d0 = d_lo; d0 <= d_hi; d0 += B) {
        const int dend = (d0 + B - 1 < d_hi) ? (d0 + B - 1) : d_hi;

        // --- acquire producer progress ---
        if (has_prod) {
            int i_need = dend - cs; if (i_need > N) i_need = N;
            if (lane == 0) {
                while (g_prog[s * 32] < i_need) { }
                __threadfence();
            }
        }
        __syncwarp();   // also protects hbuf reuse across chunks

        // --- stage halo rows [d0-cs-1 .. d0-cs-1+B] (L1-bypassed) ---
        {
            const int i_base = d0 - cs - 1;
            int ii = i_base + lane; ii = ii < 0 ? 0 : (ii > N ? N : ii);
            hbuf[w][lane] = __ldcg(&hsrc[ii]);
            if (lane == 0) {
                int i2 = i_base + B; i2 = i2 < 0 ? 0 : (i2 > N ? N : i2);
                hbuf[w][B] = __ldcg(&hsrc[i2]);
            }
            __syncwarp();
        }

        const bool steady = fullstrip && (d0 >= cs + SW) && (dend <= cs + N)
                            && (dend == d0 + B - 1);
        if (steady != was_steady) {
            // translate xw between shift-indexed and residue-indexed: reverse.
            float t0 = xw[0], t1 = xw[1];
            xw[0] = xw[3]; xw[3] = t0; xw[1] = xw[2]; xw[2] = t1;
            was_steady = steady;
        }

        if (steady) {
            const int q0 = d0 - cs - 1;                 // multiple of 32
            const int kb = (q0 >> 2) - lane;
            float* pg = g_buf + gidx(d0, j0);
            float hl = hbuf[w][0];
            int i31 = q0 - 126;                         // lane31 c=3 row at step 0
#pragma unroll 2
            for (int eb = 0; eb < B; eb += 4) {
                const int kk = kb + (eb >> 2);
                const float x0 = xs[0][kk], x1 = xs[1][kk];
                const float x2 = xs[2][kk], x3 = xs[3][kk];
                fast_step<0>(cur, oth, xw, yv, x0, hbuf[w][eb + 1], hl, lane, pg, hdst, i31);
                fast_step<1>(oth, cur, xw, yv, x1, hbuf[w][eb + 2], hl, lane, pg, hdst, i31);
                fast_step<2>(cur, oth, xw, yv, x2, hbuf[w][eb + 3], hl, lane, pg, hdst, i31);
                fast_step<3>(oth, cur, xw, yv, x3, hbuf[w][eb + 4], hl, lane, pg, hdst, i31);
            }
        } else {
            float* pg = g_buf + gidx(d0, j0);
            for (int d = d0; d <= dend; ++d) {
                const int e = d - d0;
                const int q = d - cs - 1;
                int kk = (q >> 2) - lane;
                kk = kk < 0 ? 0 : (kk >= N4 ? N4 - 1 : kk);
                const float xn = xs[q & 3][kk];
                float nl = __shfl_up_sync(0xffffffffu, cur[3], 1);
                float np = __shfl_up_sync(0xffffffffu, oth[3], 1);
                if (lane == 0) { nl = hbuf[w][e + 1]; np = hbuf[w][e]; }
                xw[3] = xw[2]; xw[2] = xw[1]; xw[1] = xw[0]; xw[0] = xn;
                float dpr = np, lft = nl;
#pragma unroll
                for (int c = 0; c < W; ++c) {
                    const int i = d - j0 - c;
                    float top = cur[c], old = oth[c];
                    float dd = xw[c] - yv[c];
                    float v = fmaf(dd, dd, fminf(fminf(top, lft), dpr));
                    oth[c] = top;
                    cur[c] = (i >= 1) ? v : DTW_INF;
                    if (i >= 1 && i <= N && (j0 + c) <= M) pg[c] = v;
                    dpr = old; lft = top;
                }
                pg += PITCH;
                if (lane == 31) {
                    const int i31 = d - j0 - 3;
                    if (has_cons && i31 >= 1 && i31 <= N) hdst[i31] = cur[3];
                }
            }
        }

        // --- release progress to consumer ---
        if (has_cons && lane == 31) {
            int ip = dend - cs - (SW - 1);
            if (ip > 0) {
                if (ip > N) ip = N;
                __threadfence();
                g_prog[(s + 1) * 32] = ip;
            }
        }
    }
}

// ---------------------------------------------------------------------------
// De-skew + sqrt: out[i][j] = sqrt(g_buf[gidx(i+j, j)]).
// ---------------------------------------------------------------------------
constexpr int TR = 128;
constexpr int TC = 32;

__global__ __launch_bounds__(256)
void dtw_deskew(float* __restrict__ out, int N, int M)
{
    __shared__ float sh[TR + TC - 1][TC];
    const int i0 = blockIdx.y * TR;
    const int j0 = blockIdx.x * TC;
    const int d0 = i0 + j0;
    const int pitch_out = M + 1;

    for (int k = threadIdx.x; k < (TR + TC - 1) * TC; k += 256) {
        int dl = k >> 5;
        int jl = k & 31;
        int dg = d0 + dl;
        int jg = j0 + jl;
        float v = 0.0f;
        if (dg <= N + M && jg <= M)
            v = g_buf[gidx(dg, jg)];
        sh[dl][jl] = v;
    }
    __syncthreads();

    for (int k = threadIdx.x; k < TR * TC; k += 256) {
        int ii = k >> 5;
        int jl = k & 31;
        int ig = i0 + ii;
        int jg = j0 + jl;
        if (ig <= N && jg <= M)
            out[(size_t)ig * pitch_out + jg] = sqrtf(sh[ii + jl][jl]);
    }
}

// ---------------------------------------------------------------------------
extern "C" void kernel_launch(void* const* d_in, const int* in_sizes, int n_in,
                              void* d_out, int out_size)
{
    const float* x = (const float*)d_in[0];
    const float* y = (const float*)d_in[1];
    float* out = (float*)d_out;
    const int N = in_sizes[0];
    const int M = in_sizes[1];

    const int nstrips = (M + SW - 1) / SW;            // 48 for M=6144
    dtw_init<<<64, 256>>>(N, M, nstrips);

    const int nblocks = (nstrips + WPB - 1) / WPB;    // 12 blocks, all resident
    dtw_wave<<<nblocks, WPB * 32>>>(x, y, N, M, nstrips);

    dim3 grid((M + 1 + TC - 1) / TC, (N + 1 + TR - 1) / TR);
    dtw_deskew<<<grid, 256>>>(out, N, M);
}

// round 8
// speedup vs baseline: 1.2088x; 1.2042x over previous
#include <cuda_runtime.h>
#include <cstdint>

#define DTW_INF 99999.0f

// Bench size: N = M = 6144.
constexpr int MAXN = 6144;
constexpr int MAXM = 6144;
constexpr int PITCH = (MAXM + 4 + 3) & ~3;    // 6148, multiple of 4

// Diagonal-major scratch: cell (i,j) at g_buf[(i+j)*PITCH + j + 3].
__device__ float g_buf[(size_t)(MAXN + MAXM + 2) * PITCH + 16];

constexpr int SW = 256;     // strip width (columns per warp/block)
constexpr int W  = 8;       // columns per lane
constexpr int B  = 64;      // steps per synchronization chunk
constexpr int MAXSTRIPS = 32;
constexpr int HALO_PITCH = MAXN + 64;
constexpr int N8MAX = MAXN / 8 + 16;

// g_halo[s][i] = v(i, cs-1): left-boundary column of strip s (written by s-1).
__device__ float g_halo[(size_t)(MAXSTRIPS + 1) * HALO_PITCH];
// g_prog[s*32] = highest row i such that g_halo[s][0..i] is published.
__device__ volatile int g_prog[(MAXSTRIPS + 1) * 32];

__device__ __forceinline__ size_t gidx(int d, int j) {
    return (size_t)d * PITCH + (j + 3);
}

// ---------------------------------------------------------------------------
__global__ void dtw_init(int N, int M, int nstrips)
{
    const int stride = gridDim.x * blockDim.x;
    const int idx = blockIdx.x * blockDim.x + threadIdx.x;
    for (int j = idx; j <= M; j += stride)
        g_buf[gidx(j, j)] = (j == 0) ? 0.0f : DTW_INF;
    for (int i = idx + 1; i <= N; i += stride)
        g_buf[gidx(i, 0)] = DTW_INF;
    for (int i = idx; i <= N; i += stride)
        g_halo[i] = (i == 0) ? 0.0f : DTW_INF;     // strip 0 left halo (col 0)
    for (int t = idx; t <= nstrips; t += stride) {
        g_prog[t * 32] = 0;
        if (t >= 1) g_halo[(size_t)t * HALO_PITCH] = DTW_INF;  // v(0, cs-1)
    }
}

// ---------------------------------------------------------------------------
// One anti-diagonal step for one warp-strip. a = diag e-1 values, b = diag e-2
// (overwritten in-place with the new diag e). xw is residue-indexed:
// xw[r] holds the x value whose index == r (mod 8); E == e & 7.
// ---------------------------------------------------------------------------
template<int E, bool ST>
__device__ __forceinline__ void phase8(
    float (&a)[W], float (&b)[W], float (&xw)[W],
    const float (&yv)[W], const int (&lim)[W],
    float xn, float nh, float& hl,
    int lane, int e, int lbase,
    float* pg, float* hdst, bool hc)
{
    float nl = __shfl_up_sync(0xffffffffu, a[W - 1], 1);   // v(i0,   j0-1)
    float np = __shfl_up_sync(0xffffffffu, b[W - 1], 1);   // v(i0-1, j0-1)
    if (lane == 0) { nl = nh; np = hl; }
    hl = nh;
    xw[E] = xn;

    float left = nl, diag = np;
#pragma unroll
    for (int c = 0; c < W; ++c) {
        float top = a[c], old = b[c];
        float dd = xw[(E - c) & (W - 1)] - yv[c];
        float v = fmaf(dd, dd, fminf(fminf(top, left), diag));
        if (ST) {
            b[c] = v;
        } else {
            int i = e + 1 - lbase - c;
            if (i >= 1 && i <= lim[c]) b[c] = v;   // freeze-on-inactive
        }
        diag = old;
        left = top;
    }

    if (ST) {
        float4* q = reinterpret_cast<float4*>(pg);
        q[0] = make_float4(b[0], b[1], b[2], b[3]);
        q[1] = make_float4(b[4], b[5], b[6], b[7]);
        if (lane == 31) hdst[e - (SW - 2)] = b[W - 1];
    } else {
#pragma unroll
        for (int c = 0; c < W; ++c) {
            int i = e + 1 - lbase - c;
            if (i >= 1 && i <= lim[c]) pg[c] = b[c];
        }
        if (lane == 31 && hc) {
            int i31 = e - (SW - 2);
            if (i31 >= 1 && i31 <= lim[W - 1]) hdst[i31] = b[W - 1];
        }
    }
}

// ---------------------------------------------------------------------------
// Persistent pipelined wavefront: one warp (one block, one SM) per 256-column
// strip. Strips synchronize through g_halo/g_prog with a 4-chunk systolic lag.
// ---------------------------------------------------------------------------
__global__ __launch_bounds__(32, 1)
void dtw_wave(const float* __restrict__ x, const float* __restrict__ y,
              int N, int M, int nstrips)
{
    __shared__ float xs[W][N8MAX];     // x deinterleaved: xs[r][k] = x[8k+r]
    __shared__ float hbuf[B + 8];      // staged halo rows for current chunk

    const int lane = threadIdx.x;
    const int s = blockIdx.x;
    const int N8 = (N + W - 1) / W;

    for (int i = lane; i < N; i += 32)
        xs[i & (W - 1)][i >> 3] = x[i];
    __syncwarp();

    const int cs = 1 + SW * s;                // first column of strip
    const int j0 = cs + W * lane;             // first column of this lane
    const int lbase = W * lane;
    const bool fullstrip = (cs + SW - 1 <= M);
    const bool has_prod = (s > 0);
    const bool has_cons = (s + 1 < nstrips) && fullstrip;

    float yv[W]; int lim[W];
#pragma unroll
    for (int c = 0; c < W; ++c) {
        bool ok = (j0 + c) <= M;
        yv[c] = ok ? y[j0 + c - 1] : 0.0f;
        lim[c] = ok ? N : 0;
    }

    float a[W], b[W], xw[W];
#pragma unroll
    for (int c = 0; c < W; ++c) { a[c] = DTW_INF; b[c] = DTW_INF; xw[c] = 0.0f; }

    const float* hsrc = g_halo + (size_t)s * HALO_PITCH;
    float* hdst = g_halo + (size_t)(s + 1) * HALO_PITCH;
    volatile int* prog_src = &g_prog[s * 32];
    volatile int* prog_dst = &g_prog[(s + 1) * 32];

    float* pg = g_buf + gidx(cs + 1, j0);     // store ptr for step e=0

    const int nsteps = N + SW;                // e in [0, nsteps)
    const int nchunks = (nsteps + B - 1) / B;

    for (int k = 0; k < nchunks; ++k) {
        const int e0 = k * B;

        // --- acquire: wait until producer published halo rows <= e0+B ---
        if (has_prod && lane == 0) {
            int need = e0 + B; if (need > N) need = N;
            if (*prog_src < need) {
                while (*prog_src < need) __nanosleep(64);
            }
            __threadfence();
        }
        __syncwarp();

        // --- stage halo rows [e0 .. e0+B] (L1-bypassing loads) ---
        {
            int r  = e0 + lane;      if (r  > N) r  = N;
            int r2 = e0 + 32 + lane; if (r2 > N) r2 = N;
            hbuf[lane]      = __ldcg(hsrc + r);
            hbuf[32 + lane] = __ldcg(hsrc + r2);
            if (lane == 0) {
                int r3 = e0 + B; if (r3 > N) r3 = N;
                hbuf[B] = __ldcg(hsrc + r3);
            }
        }
        __syncwarp();

        float hl = hbuf[0];
        const bool steady = fullstrip && (e0 >= SW) && (e0 + B <= N);
        int kxm = (e0 >> 3) - lane;

        if (steady) {
#pragma unroll 1
            for (int m = 0; m < B / W; ++m, ++kxm) {
                float xv[W];
#pragma unroll
                for (int r = 0; r < W; ++r) xv[r] = xs[r][kxm];
                const int eb = e0 + m * W;
                const int hb = m * W;
                phase8<0,true>(a,b,xw,yv,lim, xv[0], hbuf[hb+1], hl, lane, eb+0, lbase, pg, hdst, has_cons); pg += PITCH;
                phase8<1,true>(b,a,xw,yv,lim, xv[1], hbuf[hb+2], hl, lane, eb+1, lbase, pg, hdst, has_cons); pg += PITCH;
                phase8<2,true>(a,b,xw,yv,lim, xv[2], hbuf[hb+3], hl, lane, eb+2, lbase, pg, hdst, has_cons); pg += PITCH;
                phase8<3,true>(b,a,xw,yv,lim, xv[3], hbuf[hb+4], hl, lane, eb+3, lbase, pg, hdst, has_cons); pg += PITCH;
                phase8<4,true>(a,b,xw,yv,lim, xv[4], hbuf[hb+5], hl, lane, eb+4, lbase, pg, hdst, has_cons); pg += PITCH;
                phase8<5,true>(b,a,xw,yv,lim, xv[5], hbuf[hb+6], hl, lane, eb+5, lbase, pg, hdst, has_cons); pg += PITCH;
                phase8<6,true>(a,b,xw,yv,lim, xv[6], hbuf[hb+7], hl, lane, eb+6, lbase, pg, hdst, has_cons); pg += PITCH;
                phase8<7,true>(b,a,xw,yv,lim, xv[7], hbuf[hb+8], hl, lane, eb+7, lbase, pg, hdst, has_cons); pg += PITCH;
            }
        } else {
#pragma unroll 1
            for (int m = 0; m < B / W; ++m, ++kxm) {
                int kc = kxm; if (kc < 0) kc = 0; if (kc >= N8) kc = N8 - 1;
                float xv[W];
#pragma unroll
                for (int r = 0; r < W; ++r) xv[r] = xs[r][kc];
                const int eb = e0 + m * W;
                const int hb = m * W;
                phase8<0,false>(a,b,xw,yv,lim, xv[0], hbuf[hb+1], hl, lane, eb+0, lbase, pg, hdst, has_cons); pg += PITCH;
                phase8<1,false>(b,a,xw,yv,lim, xv[1], hbuf[hb+2], hl, lane, eb+1, lbase, pg, hdst, has_cons); pg += PITCH;
                phase8<2,false>(a,b,xw,yv,lim, xv[2], hbuf[hb+3], hl, lane, eb+2, lbase, pg, hdst, has_cons); pg += PITCH;
                phase8<3,false>(b,a,xw,yv,lim, xv[3], hbuf[hb+4], hl, lane, eb+3, lbase, pg, hdst, has_cons); pg += PITCH;
                phase8<4,false>(a,b,xw,yv,lim, xv[4], hbuf[hb+5], hl, lane, eb+4, lbase, pg, hdst, has_cons); pg += PITCH;
                phase8<5,false>(b,a,xw,yv,lim, xv[5], hbuf[hb+6], hl, lane, eb+5, lbase, pg, hdst, has_cons); pg += PITCH;
                phase8<6,false>(a,b,xw,yv,lim, xv[6], hbuf[hb+7], hl, lane, eb+6, lbase, pg, hdst, has_cons); pg += PITCH;
                phase8<7,false>(b,a,xw,yv,lim, xv[7], hbuf[hb+8], hl, lane, eb+7, lbase, pg, hdst, has_cons); pg += PITCH;
            }
        }

        // --- release: lane 31 publishes its own halo stores ---
        if (has_cons && lane == 31) {
            int ip = e0 + B - 1 - (SW - 2);
            if (ip > 0) {
                if (ip > N) ip = N;
                __threadfence();
                *prog_dst = ip;
            }
        }
    }
}

// ---------------------------------------------------------------------------
// De-skew + sqrt: out[i][j] = sqrt(g_buf[gidx(i+j, j)]).
// ---------------------------------------------------------------------------
constexpr int TR = 128;
constexpr int TC = 32;

__global__ __launch_bounds__(256)
void dtw_deskew(float* __restrict__ out, int N, int M)
{
    __shared__ float sh[TR + TC - 1][TC];
    const int i0 = blockIdx.y * TR;
    const int j0 = blockIdx.x * TC;
    const int d0 = i0 + j0;
    const int pitch_out = M + 1;

    for (int k = threadIdx.x; k < (TR + TC - 1) * TC; k += 256) {
        int dl = k >> 5;
        int jl = k & 31;
        int dg = d0 + dl;
        int jg = j0 + jl;
        float v = 0.0f;
        if (dg <= N + M && jg <= M)
            v = g_buf[gidx(dg, jg)];
        sh[dl][jl] = v;
    }
    __syncthreads();

    for (int k = threadIdx.x; k < TR * TC; k += 256) {
        int ii = k >> 5;
        int jl = k & 31;
        int ig = i0 + ii;
        int jg = j0 + jl;
        if (ig <= N && jg <= M)
            out[(size_t)ig * pitch_out + jg] = sqrtf(sh[ii + jl][jl]);
    }
}

// ---------------------------------------------------------------------------
extern "C" void kernel_launch(void* const* d_in, const int* in_sizes, int n_in,
                              void* d_out, int out_size)
{
    const float* x = (const float*)d_in[0];
    const float* y = (const float*)d_in[1];
    float* out = (float*)d_out;
    const int N = in_sizes[0];
    const int M = in_sizes[1];

    const int nstrips = (M + SW - 1) / SW;          // 24 for M=6144
    dtw_init<<<64, 256>>>(N, M, nstrips);

    dtw_wave<<<nstrips, 32>>>(x, y, N, M, nstrips); // one warp per SM-strip

    dim3 grid((M + 1 + TC - 1) / TC, (N + 1 + TR - 1) / TR);
    dtw_deskew<<<grid, 256>>>(out, N, M);
}

// round 9
// speedup vs baseline: 4.3277x; 3.5803x over previous
#include <cuda_runtime.h>
#include <cstdint>

#define DTW_INF 99999.0f

// Bench size: N = M = 6144.
constexpr int MAXN = 6144;
constexpr int MAXM = 6144;
constexpr int PITCH = (MAXM + 4 + 3) & ~3;    // 6148, multiple of 4

// Diagonal-major scratch: cell (i,j) at g_buf[(i+j)*PITCH + j + 3].
__device__ float g_buf[(size_t)(MAXN + MAXM + 2) * PITCH + 16];

constexpr int SW = 256;     // strip width (columns per warp)
constexpr int W  = 8;       // columns per lane
constexpr int B  = 256;     // steps per launch-chunk
constexpr int LAG = 2;      // chunk lag between adjacent strips (B*(LAG-1) >= SW-1)
constexpr int MAXSTRIPS = 32;
constexpr int HALO_PITCH = MAXN + 64;

// g_halo[s][i] = v(i, cs-1): left-boundary column of strip s (written by s-1).
__device__ float g_halo[(size_t)(MAXSTRIPS + 1) * HALO_PITCH];
// Persistent per-lane DP state between launches: [strip][reg 0..15][lane].
__device__ float g_state[MAXSTRIPS][2 * W][32];

__device__ __forceinline__ size_t gidx(int d, int j) {
    return (size_t)d * PITCH + (j + 3);
}

// ---------------------------------------------------------------------------
__global__ void dtw_init(int N, int M, int nstrips)
{
    const int stride = gridDim.x * blockDim.x;
    const int idx = blockIdx.x * blockDim.x + threadIdx.x;
    for (int j = idx; j <= M; j += stride)
        g_buf[gidx(j, j)] = (j == 0) ? 0.0f : DTW_INF;
    for (int i = idx + 1; i <= N; i += stride)
        g_buf[gidx(i, 0)] = DTW_INF;
    for (int i = idx; i <= N; i += stride)
        g_halo[i] = (i == 0) ? 0.0f : DTW_INF;      // strip 0 left halo (col 0)
    for (int t = idx + 1; t <= nstrips; t += stride)
        g_halo[(size_t)t * HALO_PITCH] = DTW_INF;   // v(0, cs-1)
}

// ---------------------------------------------------------------------------
// One anti-diagonal step. a = diag e-1 values, b = diag e-2 (overwritten with
// diag e). xw residue-indexed: xw[r] holds x whose index == r (mod 8).
// ibase = i of lane's c=0 cell = e+1-8*lane. hok = halo-row-store valid.
// ---------------------------------------------------------------------------
template<int E, bool ST>
__device__ __forceinline__ void phase(
    float (&a)[W], float (&b)[W], float (&xw)[W],
    const float (&yv)[W], const int (&limR)[W],
    float xn, float nh, float& hl, bool is0, int lane,
    int ibase, bool hok, float* pg, float* hq)
{
    float nl = __shfl_up_sync(0xffffffffu, a[W - 1], 1);   // v(i0,   j0-1)
    float np = __shfl_up_sync(0xffffffffu, b[W - 1], 1);   // v(i0-1, j0-1)
    if (is0) { nl = nh; np = hl; }
    hl = nh;
    xw[E] = xn;

    float left = nl, diag = np;
#pragma unroll
    for (int c = 0; c < W; ++c) {
        float top = a[c], old = b[c];
        float dd = xw[(E - c) & (W - 1)] - yv[c];
        float v = fmaf(dd, dd, fminf(fminf(top, left), diag));
        if (ST) {
            b[c] = v;
        } else {
            int i = ibase - c;
            if (i >= 1 && i <= limR[c]) b[c] = v;     // freeze when inactive
        }
        diag = old; left = top;
    }

    if (ST) {
        float4* q = reinterpret_cast<float4*>(pg);
        q[0] = make_float4(b[0], b[1], b[2], b[3]);
        q[1] = make_float4(b[4], b[5], b[6], b[7]);
        if (lane == 31) *hq = b[W - 1];
    } else {
#pragma unroll
        for (int c = 0; c < W; ++c) {
            int i = ibase - c;
            if (i >= 1 && i <= limR[c]) pg[c] = b[c];
        }
        if (lane == 31 && hok) *hq = b[W - 1];
    }
}

// ---------------------------------------------------------------------------
// Chunk-diagonal kernel: launch g advances strip s by B steps on chunk
// c = g - LAG*s. Kernel boundaries provide producer->consumer ordering.
// ---------------------------------------------------------------------------
__global__ __launch_bounds__(32, 1)
void dtw_chunk(const float* __restrict__ x, const float* __restrict__ y,
               int N, int M, int g)
{
    const int s = blockIdx.x;
    const int nchunks = (N + SW + B - 1) / B;
    const int c = g - LAG * s;
    if (c < 0 || c >= nchunks) return;

    __shared__ float hbuf[B + 1];       // halo rows e0..e0+B
    __shared__ float xsw[W][65];        // x window, residue-deinterleaved

    const int lane = threadIdx.x;
    const int e0 = c * B;
    const int cs = 1 + SW * s;
    const int j0 = cs + W * lane;
    const bool is0 = (lane == 0);

    // --- stage halo chunk (written by strip s-1 in earlier launches) ---
    {
        const float* hsrc = g_halo + (size_t)s * HALO_PITCH;
        for (int t = lane; t < B + 1; t += 32) {
            int r = e0 + t; if (r > N) r = N;
            hbuf[t] = hsrc[r];
        }
    }
    // --- stage x window: idx = e0-256 .. e0+255 ;  xsw[r][k] = x[w0+8k+r] ---
    {
        const int w0 = e0 - 256;
        for (int t = lane; t < 512; t += 32) {
            int idx = w0 + t;
            idx = idx < 0 ? 0 : (idx >= N ? N - 1 : idx);
            xsw[t & (W - 1)][t >> 3] = x[idx];
        }
    }
    __syncwarp();

    float yv[W]; int limR[W];
#pragma unroll
    for (int q = 0; q < W; ++q) {
        bool ok = (j0 + q) <= M;
        yv[q] = ok ? y[j0 + q - 1] : 0.0f;
        limR[q] = ok ? N : 0;
    }

    // --- DP state ---
    float a[W], b[W], xw[W];
    if (c == 0) {
#pragma unroll
        for (int q = 0; q < W; ++q) { a[q] = DTW_INF; b[q] = DTW_INF; }
    } else {
#pragma unroll
        for (int q = 0; q < W; ++q) {
            a[q] = g_state[s][q][lane];
            b[q] = g_state[s][W + q][lane];
        }
    }
#pragma unroll
    for (int r = 0; r < W; ++r)
        xw[r] = xsw[r][31 - lane];          // x indices e0-8lane-8+r

    float hl = hbuf[0];
    float* pg = g_buf + gidx(cs + 1 + e0, j0);
    float* hq = g_halo + (size_t)(s + 1) * HALO_PITCH + (e0 - (SW - 2));

    const bool steady = (e0 >= SW) && (e0 + B <= N) && (cs + SW - 1 <= M);

    if (steady) {
#pragma unroll 1
        for (int m = 0; m < B / W; ++m) {
            const int kk = 32 + m - lane;
            float xv[W];
#pragma unroll
            for (int r = 0; r < W; ++r) xv[r] = xsw[r][kk];
            const int hb = m * W;
            phase<0,true>(a,b,xw,yv,limR, xv[0], hbuf[hb+1], hl, is0, lane, 0, true, pg, hq); pg += PITCH; ++hq;
            phase<1,true>(b,a,xw,yv,limR, xv[1], hbuf[hb+2], hl, is0, lane, 0, true, pg, hq); pg += PITCH; ++hq;
            phase<2,true>(a,b,xw,yv,limR, xv[2], hbuf[hb+3], hl, is0, lane, 0, true, pg, hq); pg += PITCH; ++hq;
            phase<3,true>(b,a,xw,yv,limR, xv[3], hbuf[hb+4], hl, is0, lane, 0, true, pg, hq); pg += PITCH; ++hq;
            phase<4,true>(a,b,xw,yv,limR, xv[4], hbuf[hb+5], hl, is0, lane, 0, true, pg, hq); pg += PITCH; ++hq;
            phase<5,true>(b,a,xw,yv,limR, xv[5], hbuf[hb+6], hl, is0, lane, 0, true, pg, hq); pg += PITCH; ++hq;
            phase<6,true>(a,b,xw,yv,limR, xv[6], hbuf[hb+7], hl, is0, lane, 0, true, pg, hq); pg += PITCH; ++hq;
            phase<7,true>(b,a,xw,yv,limR, xv[7], hbuf[hb+8], hl, is0, lane, 0, true, pg, hq); pg += PITCH; ++hq;
        }
    } else {
        int ib = e0 + 1 - W * lane;         // ibase at first step of chunk
#pragma unroll 1
        for (int m = 0; m < B / W; ++m) {
            const int kk = 32 + m - lane;
            float xv[W];
#pragma unroll
            for (int r = 0; r < W; ++r) xv[r] = xsw[r][kk];
            const int hb = m * W;
            const int e = e0 + m * W;
#pragma unroll
            for (int ph = 0; ph < W; ++ph) {
                int i31 = (e + ph) - (SW - 2);
                bool hok = (i31 >= 1) && (i31 <= N);
                switch (ph) {   // compile-time unrolled: alternates a/b
                    case 0: phase<0,false>(a,b,xw,yv,limR, xv[0], hbuf[hb+1], hl, is0, lane, ib+0, hok, pg, hq); break;
                    case 1: phase<1,false>(b,a,xw,yv,limR, xv[1], hbuf[hb+2], hl, is0, lane, ib+1, hok, pg, hq); break;
                    case 2: phase<2,false>(a,b,xw,yv,limR, xv[2], hbuf[hb+3], hl, is0, lane, ib+2, hok, pg, hq); break;
                    case 3: phase<3,false>(b,a,xw,yv,limR, xv[3], hbuf[hb+4], hl, is0, lane, ib+3, hok, pg, hq); break;
                    case 4: phase<4,false>(a,b,xw,yv,limR, xv[4], hbuf[hb+5], hl, is0, lane, ib+4, hok, pg, hq); break;
                    case 5: phase<5,false>(b,a,xw,yv,limR, xv[5], hbuf[hb+6], hl, is0, lane, ib+5, hok, pg, hq); break;
                    case 6: phase<6,false>(a,b,xw,yv,limR, xv[6], hbuf[hb+7], hl, is0, lane, ib+6, hok, pg, hq); break;
                    case 7: phase<7,false>(b,a,xw,yv,limR, xv[7], hbuf[hb+8], hl, is0, lane, ib+7, hok, pg, hq); break;
                }
                pg += PITCH; ++hq;
            }
            ib += W;
        }
    }

    // --- persist DP state for the next chunk of this strip ---
#pragma unroll
    for (int q = 0; q < W; ++q) {
        g_state[s][q][lane]     = a[q];
        g_state[s][W + q][lane] = b[q];
    }
}

// ---------------------------------------------------------------------------
// De-skew + sqrt: out[i][j] = sqrt(g_buf[gidx(i+j, j)]).
// ---------------------------------------------------------------------------
constexpr int TR = 128;
constexpr int TC = 32;

__global__ __launch_bounds__(256)
void dtw_deskew(float* __restrict__ out, int N, int M)
{
    __shared__ float sh[TR + TC - 1][TC];
    const int i0 = blockIdx.y * TR;
    const int j0 = blockIdx.x * TC;
    const int d0 = i0 + j0;
    const int pitch_out = M + 1;

    for (int k = threadIdx.x; k < (TR + TC - 1) * TC; k += 256) {
        int dl = k >> 5;
        int jl = k & 31;
        int dg = d0 + dl;
        int jg = j0 + jl;
        float v = 0.0f;
        if (dg <= N + M && jg <= M)
            v = g_buf[gidx(dg, jg)];
        sh[dl][jl] = v;
    }
    __syncthreads();

    for (int k = threadIdx.x; k < TR * TC; k += 256) {
        int ii = k >> 5;
        int jl = k & 31;
        int ig = i0 + ii;
        int jg = j0 + jl;
        if (ig <= N && jg <= M)
            out[(size_t)ig * pitch_out + jg] = sqrtf(sh[ii + jl][jl]);
    }
}

// ---------------------------------------------------------------------------
extern "C" void kernel_launch(void* const* d_in, const int* in_sizes, int n_in,
                              void* d_out, int out_size)
{
    const float* x = (const float*)d_in[0];
    const float* y = (const float*)d_in[1];
    float* out = (float*)d_out;
    const int N = in_sizes[0];
    const int M = in_sizes[1];

    const int nstrips = (M + SW - 1) / SW;              // 24
    const int nchunks = (N + SW + B - 1) / B;           // 25
    const int G = (nchunks - 1) + LAG * (nstrips - 1) + 1;   // 71

    dtw_init<<<64, 256>>>(N, M, nstrips);

    for (int g = 0; g < G; ++g)
        dtw_chunk<<<nstrips, 32>>>(x, y, N, M, g);

    dim3 grid((M + 1 + TC - 1) / TC, (N + 1 + TR - 1) / TR);
    dtw_deskew<<<grid, 256>>>(out, N, M);
}

// round 10
// speedup vs baseline: 4.4491x; 1.0280x over previous
#include <cuda_runtime.h>
#include <cstdint>

#define DTW_INF 99999.0f

// Bench size: N = M = 6144.
constexpr int MAXN = 6144;
constexpr int MAXM = 6144;
constexpr int PITCH = (MAXM + 4 + 3) & ~3;    // 6148, multiple of 4

// Diagonal-major scratch: cell (i,j) at g_buf[(i+j)*PITCH + j + 3].
__device__ float g_buf[(size_t)(MAXN + MAXM + 2) * PITCH + 16];

constexpr int SW = 256;     // strip width (columns per warp)
constexpr int W  = 8;       // columns per lane
constexpr int B  = 256;     // steps per launch-chunk
constexpr int LAG = 2;      // chunk lag between adjacent strips (B*(LAG-1) >= SW-1)
constexpr int MAXSTRIPS = 32;
constexpr int HALO_PITCH = MAXN + 64;   // 6208, multiple of 4
constexpr int HSH = 2;      // halo index shift (16B-aligns batched stores)

// g_halo[s][HSH + i] = v(i, cs-1): left-boundary column of strip s.
__device__ float g_halo[(size_t)(MAXSTRIPS + 1) * HALO_PITCH];
// Persistent per-lane DP state between launches: [strip][reg 0..15][lane].
__device__ float g_state[MAXSTRIPS][2 * W][32];

__device__ __forceinline__ size_t gidx(int d, int j) {
    return (size_t)d * PITCH + (j + 3);
}

// ---------------------------------------------------------------------------
__global__ void dtw_init(int N, int M, int nstrips)
{
    const int stride = gridDim.x * blockDim.x;
    const int idx = blockIdx.x * blockDim.x + threadIdx.x;
    for (int j = idx; j <= M; j += stride)
        g_buf[gidx(j, j)] = (j == 0) ? 0.0f : DTW_INF;
    for (int i = idx + 1; i <= N; i += stride)
        g_buf[gidx(i, 0)] = DTW_INF;
    for (int i = idx; i <= N; i += stride)
        g_halo[HSH + i] = (i == 0) ? 0.0f : DTW_INF;   // strip 0 halo (col 0)
    for (int t = idx + 1; t <= nstrips; t += stride)
        g_halo[(size_t)t * HALO_PITCH + HSH] = DTW_INF;  // v(0, cs-1)
}

// ---------------------------------------------------------------------------
// One anti-diagonal step. a = diag e-1 values, b = diag e-2 (overwritten with
// diag e). xw residue-indexed: xw[r] holds x whose index == r (mod 8).
// nh_new/nh_old: halo rows for lane 0 (preloaded into registers).
// Steady (ST=true): unguarded, immediate-offset store, edge value to hsave.
// ---------------------------------------------------------------------------
template<int E, bool ST>
__device__ __forceinline__ void phase(
    float (&a)[W], float (&b)[W], float (&xw)[W],
    const float (&yv)[W], const int (&limR)[W],
    float xn, float nh_new, float nh_old, bool is0, int lane,
    int ibase, bool hok, float* pg, float* hq, float& hsave)
{
    float nl = __shfl_up_sync(0xffffffffu, a[W - 1], 1);   // v(i0,   j0-1)
    float np = __shfl_up_sync(0xffffffffu, b[W - 1], 1);   // v(i0-1, j0-1)
    if (is0) { nl = nh_new; np = nh_old; }
    xw[E] = xn;

    float left = nl, diag = np;
#pragma unroll
    for (int c = 0; c < W; ++c) {
        float top = a[c], old = b[c];
        float dd = xw[(E - c) & (W - 1)] - yv[c];
        float v = fmaf(dd, dd, fminf(fminf(top, left), diag));
        if (ST) {
            b[c] = v;
        } else {
            int i = ibase - c;
            if (i >= 1 && i <= limR[c]) b[c] = v;     // freeze when inactive
        }
        diag = old; left = top;
    }

    if (ST) {
        float4* q = reinterpret_cast<float4*>(pg);
        q[0] = make_float4(b[0], b[1], b[2], b[3]);
        q[1] = make_float4(b[4], b[5], b[6], b[7]);
        hsave = b[W - 1];
    } else {
#pragma unroll
        for (int c = 0; c < W; ++c) {
            int i = ibase - c;
            if (i >= 1 && i <= limR[c]) pg[c] = b[c];
        }
        if (lane == 31 && hok) *hq = b[W - 1];
    }
}

// ---------------------------------------------------------------------------
// Chunk-diagonal kernel: launch g advances strip s = s0 + blockIdx.x by B
// steps on chunk c = g - LAG*s. Kernel boundaries provide ordering.
// ---------------------------------------------------------------------------
__global__ __launch_bounds__(32, 1)
void dtw_chunk(const float* __restrict__ x, const float* __restrict__ y,
               int N, int M, int g, int s0)
{
    const int s = s0 + blockIdx.x;
    const int nchunks = (N + SW + B - 1) / B;
    const int c = g - LAG * s;
    if (c < 0 || c >= nchunks) return;

    __shared__ float hbuf[B + 1];       // halo rows e0..e0+B
    __shared__ float xsw[W][65];        // x window, residue-deinterleaved

    const int lane = threadIdx.x;
    const int e0 = c * B;
    const int cs = 1 + SW * s;
    const int j0 = cs + W * lane;
    const bool is0 = (lane == 0);

    // --- stage halo chunk (written by strip s-1 in earlier launches) ---
    {
        const float* hsrc = g_halo + (size_t)s * HALO_PITCH + HSH;
        for (int t = lane; t < B + 1; t += 32) {
            int r = e0 + t; if (r > N) r = N;
            hbuf[t] = hsrc[r];
        }
    }
    // --- stage x window: idx = e0-256 .. e0+255 ;  xsw[r][k] = x[w0+8k+r] ---
    {
        const int w0 = e0 - 256;
        for (int t = lane; t < 512; t += 32) {
            int idx = w0 + t;
            idx = idx < 0 ? 0 : (idx >= N ? N - 1 : idx);
            xsw[t & (W - 1)][t >> 3] = x[idx];
        }
    }
    __syncwarp();

    float yv[W]; int limR[W];
#pragma unroll
    for (int q = 0; q < W; ++q) {
        bool ok = (j0 + q) <= M;
        yv[q] = ok ? y[j0 + q - 1] : 0.0f;
        limR[q] = ok ? N : 0;
    }

    // --- DP state ---
    float a[W], b[W], xw[W];
    if (c == 0) {
#pragma unroll
        for (int q = 0; q < W; ++q) { a[q] = DTW_INF; b[q] = DTW_INF; }
    } else {
#pragma unroll
        for (int q = 0; q < W; ++q) {
            a[q] = g_state[s][q][lane];
            b[q] = g_state[s][W + q][lane];
        }
    }
#pragma unroll
    for (int r = 0; r < W; ++r)
        xw[r] = xsw[r][31 - lane];          // x indices e0-8lane-8+r

    float* pg = g_buf + gidx(cs + 1 + e0, j0);
    float* hq0 = g_halo + (size_t)(s + 1) * HALO_PITCH + HSH + (e0 - (SW - 2));

    const bool steady = (e0 >= SW) && (e0 + B <= N) && (cs + SW - 1 <= M);
    float hdum;

    if (steady) {
#pragma unroll 1
        for (int m = 0; m < B / W; ++m) {
            const int kk = 32 + m - lane;
            float xv[W], nhv[9], hs[8];
#pragma unroll
            for (int r = 0; r < W; ++r) xv[r] = xsw[r][kk];
            const int hb = m * W;
#pragma unroll
            for (int r = 0; r < 9; ++r) nhv[r] = hbuf[hb + r];
            phase<0,true>(a,b,xw,yv,limR, xv[0], nhv[1], nhv[0], is0, lane, 0, true, pg + 0*PITCH, hq0, hs[0]);
            phase<1,true>(b,a,xw,yv,limR, xv[1], nhv[2], nhv[1], is0, lane, 0, true, pg + 1*PITCH, hq0, hs[1]);
            phase<2,true>(a,b,xw,yv,limR, xv[2], nhv[3], nhv[2], is0, lane, 0, true, pg + 2*PITCH, hq0, hs[2]);
            phase<3,true>(b,a,xw,yv,limR, xv[3], nhv[4], nhv[3], is0, lane, 0, true, pg + 3*PITCH, hq0, hs[3]);
            phase<4,true>(a,b,xw,yv,limR, xv[4], nhv[5], nhv[4], is0, lane, 0, true, pg + 4*PITCH, hq0, hs[4]);
            phase<5,true>(b,a,xw,yv,limR, xv[5], nhv[6], nhv[5], is0, lane, 0, true, pg + 5*PITCH, hq0, hs[5]);
            phase<6,true>(a,b,xw,yv,limR, xv[6], nhv[7], nhv[6], is0, lane, 0, true, pg + 6*PITCH, hq0, hs[6]);
            phase<7,true>(b,a,xw,yv,limR, xv[7], nhv[8], nhv[7], is0, lane, 0, true, pg + 7*PITCH, hq0, hs[7]);
            if (lane == 31) {
                float4* hqv = reinterpret_cast<float4*>(hq0 + 8 * m);  // 16B aligned via HSH
                hqv[0] = make_float4(hs[0], hs[1], hs[2], hs[3]);
                hqv[1] = make_float4(hs[4], hs[5], hs[6], hs[7]);
            }
            pg += 8 * PITCH;
        }
    } else {
        float* hq = hq0;
        int ib = e0 + 1 - W * lane;         // ibase at first step of chunk
#pragma unroll 1
        for (int m = 0; m < B / W; ++m) {
            const int kk = 32 + m - lane;
            float xv[W], nhv[9];
#pragma unroll
            for (int r = 0; r < W; ++r) xv[r] = xsw[r][kk];
            const int hb = m * W;
#pragma unroll
            for (int r = 0; r < 9; ++r) nhv[r] = hbuf[hb + r];
            const int e = e0 + m * W;
#pragma unroll
            for (int ph = 0; ph < W; ++ph) {
                int i31 = (e + ph) - (SW - 2);
                bool hok = (i31 >= 1) && (i31 <= N);
                switch (ph) {   // compile-time unrolled: alternates a/b
                    case 0: phase<0,false>(a,b,xw,yv,limR, xv[0], nhv[1], nhv[0], is0, lane, ib+0, hok, pg + 0*PITCH, hq, hdum); break;
                    case 1: phase<1,false>(b,a,xw,yv,limR, xv[1], nhv[2], nhv[1], is0, lane, ib+1, hok, pg + 1*PITCH, hq, hdum); break;
                    case 2: phase<2,false>(a,b,xw,yv,limR, xv[2], nhv[3], nhv[2], is0, lane, ib+2, hok, pg + 2*PITCH, hq, hdum); break;
                    case 3: phase<3,false>(b,a,xw,yv,limR, xv[3], nhv[4], nhv[3], is0, lane, ib+3, hok, pg + 3*PITCH, hq, hdum); break;
                    case 4: phase<4,false>(a,b,xw,yv,limR, xv[4], nhv[5], nhv[4], is0, lane, ib+4, hok, pg + 4*PITCH, hq, hdum); break;
                    case 5: phase<5,false>(b,a,xw,yv,limR, xv[5], nhv[6], nhv[5], is0, lane, ib+5, hok, pg + 5*PITCH, hq, hdum); break;
                    case 6: phase<6,false>(a,b,xw,yv,limR, xv[6], nhv[7], nhv[6], is0, lane, ib+6, hok, pg + 6*PITCH, hq, hdum); break;
                    case 7: phase<7,false>(b,a,xw,yv,limR, xv[7], nhv[8], nhv[7], is0, lane, ib+7, hok, pg + 7*PITCH, hq, hdum); break;
                }
                ++hq;
            }
            pg += 8 * PITCH;
            ib += W;
        }
    }

    // --- persist DP state for the next chunk of this strip ---
#pragma unroll
    for (int q = 0; q < W; ++q) {
        g_state[s][q][lane]     = a[q];
        g_state[s][W + q][lane] = b[q];
    }
}

// ---------------------------------------------------------------------------
// De-skew + sqrt: out[i][j] = sqrt(g_buf[gidx(i+j, j)]).
// ---------------------------------------------------------------------------
constexpr int TR = 128;
constexpr int TC = 32;

__global__ __launch_bounds__(256)
void dtw_deskew(float* __restrict__ out, int N, int M)
{
    __shared__ float sh[TR + TC - 1][TC];
    const int i0 = blockIdx.y * TR;
    const int j0 = blockIdx.x * TC;
    const int d0 = i0 + j0;
    const int pitch_out = M + 1;

    for (int k = threadIdx.x; k < (TR + TC - 1) * TC; k += 256) {
        int dl = k >> 5;
        int jl = k & 31;
        int dg = d0 + dl;
        int jg = j0 + jl;
        float v = 0.0f;
        if (dg <= N + M && jg <= M)
            v = g_buf[gidx(dg, jg)];
        sh[dl][jl] = v;
    }
    __syncthreads();

    for (int k = threadIdx.x; k < TR * TC; k += 256) {
        int ii = k >> 5;
        int jl = k & 31;
        int ig = i0 + ii;
        int jg = j0 + jl;
        if (ig <= N && jg <= M)
            out[(size_t)ig * pitch_out + jg] = sqrtf(sh[ii + jl][jl]);
    }
}

// ---------------------------------------------------------------------------
extern "C" void kernel_launch(void* const* d_in, const int* in_sizes, int n_in,
                              void* d_out, int out_size)
{
    const float* x = (const float*)d_in[0];
    const float* y = (const float*)d_in[1];
    float* out = (float*)d_out;
    const int N = in_sizes[0];
    const int M = in_sizes[1];

    const int nstrips = (M + SW - 1) / SW;              // 24
    const int nchunks = (N + SW + B - 1) / B;           // 25
    const int G = (nchunks - 1) + LAG * (nstrips - 1) + 1;   // 71

    dtw_init<<<64, 256>>>(N, M, nstrips);

    for (int g = 0; g < G; ++g) {
        int s_min = (g - (nchunks - 1) + LAG - 1) / LAG;
        if (s_min < 0) s_min = 0;
        int s_max = g / LAG;
        if (s_max > nstrips - 1) s_max = nstrips - 1;
        if (s_max < s_min) continue;
        dtw_chunk<<<s_max - s_min + 1, 32>>>(x, y, N, M, g, s_min);
    }

    dim3 grid((M + 1 + TC - 1) / TC, (N + 1 + TR - 1) / TR);
    dtw_deskew<<<grid, 256>>>(out, N, M);
}

// round 11
// speedup vs baseline: 6.4864x; 1.4579x over previous
#include <cuda_runtime.h>
#include <cstdint>

#define DTW_INF 99999.0f

// Bench size: N = M = 6144.
constexpr int MAXN = 6144;
constexpr int MAXM = 6144;
constexpr int PITCH = (MAXM + 4 + 3) & ~3;    // 6148, multiple of 4

// Diagonal-major scratch: cell (i,j) at g_buf[(i+j)*PITCH + j + 3].
__device__ float g_buf[(size_t)(MAXN + MAXM + 2) * PITCH + 16];

constexpr int SW = 128;     // strip width (columns per warp)
constexpr int W  = 4;       // columns per lane
constexpr int B  = 128;     // steps per launch-chunk
constexpr int LAG = 2;      // chunk lag between adjacent strips (B*(LAG-1) >= SW-1)
constexpr int MAXSTRIPS = 64;
constexpr int HALO_PITCH = MAXN + 64;   // multiple of 4
constexpr int HSH = 2;      // halo index shift (16B-aligns batched stores)

// g_halo[s][HSH + i] = v(i, cs-1): left-boundary column of strip s.
__device__ float g_halo[(size_t)(MAXSTRIPS + 1) * HALO_PITCH];
// Persistent per-lane DP state between launches: [strip][reg 0..7][lane].
__device__ float g_state[MAXSTRIPS][2 * W][32];

__device__ __forceinline__ size_t gidx(int d, int j) {
    return (size_t)d * PITCH + (j + 3);
}

// ---------------------------------------------------------------------------
__global__ void dtw_init(int N, int M, int nstrips)
{
    const int stride = gridDim.x * blockDim.x;
    const int idx = blockIdx.x * blockDim.x + threadIdx.x;
    for (int j = idx; j <= M; j += stride)
        g_buf[gidx(j, j)] = (j == 0) ? 0.0f : DTW_INF;
    for (int i = idx + 1; i <= N; i += stride)
        g_buf[gidx(i, 0)] = DTW_INF;
    for (int i = idx; i <= N; i += stride)
        g_halo[HSH + i] = (i == 0) ? 0.0f : DTW_INF;   // strip 0 halo (col 0)
    for (int t = idx + 1; t <= nstrips; t += stride)
        g_halo[(size_t)t * HALO_PITCH + HSH] = DTW_INF;  // v(0, cs-1)
}

// ---------------------------------------------------------------------------
// One anti-diagonal step. a = diag e-1 values, b = diag e-2 (overwritten with
// diag e). xw residue-indexed: xw[r] holds x whose index == r (mod 4).
// ---------------------------------------------------------------------------
template<int E, bool ST>
__device__ __forceinline__ void phase(
    float (&a)[W], float (&b)[W], float (&xw)[W],
    const float (&yv)[W], const int (&limR)[W],
    float xn, float nh_new, float nh_old, bool is0, int lane,
    int ibase, bool hok, float* pg, float* hq, float& hsave)
{
    float nl = __shfl_up_sync(0xffffffffu, a[W - 1], 1);   // v(i0,   j0-1)
    float np = __shfl_up_sync(0xffffffffu, b[W - 1], 1);   // v(i0-1, j0-1)
    if (is0) { nl = nh_new; np = nh_old; }
    xw[E] = xn;

    float left = nl, diag = np;
#pragma unroll
    for (int c = 0; c < W; ++c) {
        float top = a[c], old = b[c];
        float dd = xw[(E - c) & (W - 1)] - yv[c];
        float v = fmaf(dd, dd, fminf(fminf(top, left), diag));
        if (ST) {
            b[c] = v;
        } else {
            int i = ibase - c;
            if (i >= 1 && i <= limR[c]) b[c] = v;     // freeze when inactive
        }
        diag = old; left = top;
    }

    if (ST) {
        *reinterpret_cast<float4*>(pg) = make_float4(b[0], b[1], b[2], b[3]);
        hsave = b[W - 1];
    } else {
#pragma unroll
        for (int c = 0; c < W; ++c) {
            int i = ibase - c;
            if (i >= 1 && i <= limR[c]) pg[c] = b[c];
        }
        if (lane == 31 && hok) *hq = b[W - 1];
    }
}

// ---------------------------------------------------------------------------
// Chunk-diagonal kernel: launch g advances strip s = s0 + blockIdx.x by B
// steps on chunk c = g - LAG*s. Kernel boundaries provide ordering.
// ---------------------------------------------------------------------------
__global__ __launch_bounds__(32, 1)
void dtw_chunk(const float* __restrict__ x, const float* __restrict__ y,
               int N, int M, int g, int s0)
{
    const int s = s0 + blockIdx.x;
    const int nchunks = (N + SW + B - 1) / B;
    const int c = g - LAG * s;
    if (c < 0 || c >= nchunks) return;

    __shared__ float hbuf[B + 1];       // halo rows e0..e0+B
    __shared__ float xsw[W][65];        // x window, residue-deinterleaved

    const int lane = threadIdx.x;
    const int e0 = c * B;
    const int cs = 1 + SW * s;
    const int j0 = cs + W * lane;
    const bool is0 = (lane == 0);

    // --- stage halo chunk (written by strip s-1 in earlier launches) ---
    {
        const float* hsrc = g_halo + (size_t)s * HALO_PITCH + HSH;
#pragma unroll
        for (int t0 = 0; t0 < B + 1; t0 += 32) {
            int t = t0 + lane;
            if (t < B + 1) {
                int r = e0 + t; if (r > N) r = N;
                hbuf[t] = hsrc[r];
            }
        }
    }
    // --- stage x window: idx = e0-128 .. e0+127 ;  xsw[r][k] = x[w0+4k+r] ---
    {
        const int w0 = e0 - 128;
#pragma unroll
        for (int t0 = 0; t0 < 256; t0 += 32) {
            int t = t0 + lane;
            int idx = w0 + t;
            idx = idx < 0 ? 0 : (idx >= N ? N - 1 : idx);
            xsw[t & (W - 1)][t >> 2] = x[idx];
        }
    }
    __syncwarp();

    float yv[W]; int limR[W];
#pragma unroll
    for (int q = 0; q < W; ++q) {
        bool ok = (j0 + q) <= M;
        yv[q] = ok ? y[j0 + q - 1] : 0.0f;
        limR[q] = ok ? N : 0;
    }

    // --- DP state ---
    float a[W], b[W], xw[W];
    if (c == 0) {
#pragma unroll
        for (int q = 0; q < W; ++q) { a[q] = DTW_INF; b[q] = DTW_INF; }
    } else {
#pragma unroll
        for (int q = 0; q < W; ++q) {
            a[q] = g_state[s][q][lane];
            b[q] = g_state[s][W + q][lane];
        }
    }
#pragma unroll
    for (int r = 0; r < W; ++r)
        xw[r] = xsw[r][31 - lane];          // x indices e0-4*lane-4+r

    float* pg = g_buf + gidx(cs + 1 + e0, j0);
    float* hq0 = g_halo + (size_t)(s + 1) * HALO_PITCH + HSH + (e0 - (SW - 2));

    const bool steady = (e0 >= SW) && (e0 + B <= N) && (cs + SW - 1 <= M);
    float hdum;

    if (steady) {
#pragma unroll 1
        for (int m = 0; m < B / W; ++m) {
            const int kk = 32 + m - lane;
            float xv[W], nhv[W + 1], hs[W];
#pragma unroll
            for (int r = 0; r < W; ++r) xv[r] = xsw[r][kk];
#pragma unroll
            for (int r = 0; r < W + 1; ++r) nhv[r] = hbuf[W * m + r];
            phase<0,true>(a,b,xw,yv,limR, xv[0], nhv[1], nhv[0], is0, lane, 0, true, pg + 0*PITCH, hq0, hs[0]);
            phase<1,true>(b,a,xw,yv,limR, xv[1], nhv[2], nhv[1], is0, lane, 0, true, pg + 1*PITCH, hq0, hs[1]);
            phase<2,true>(a,b,xw,yv,limR, xv[2], nhv[3], nhv[2], is0, lane, 0, true, pg + 2*PITCH, hq0, hs[2]);
            phase<3,true>(b,a,xw,yv,limR, xv[3], nhv[4], nhv[3], is0, lane, 0, true, pg + 3*PITCH, hq0, hs[3]);
            if (lane == 31) {
                *reinterpret_cast<float4*>(hq0 + W * m) =   // 16B aligned via HSH
                    make_float4(hs[0], hs[1], hs[2], hs[3]);
            }
            pg += W * PITCH;
        }
    } else {
        float* hq = hq0;
        int ib = e0 + 1 - W * lane;         // ibase at first step of chunk
#pragma unroll 1
        for (int m = 0; m < B / W; ++m) {
            const int kk = 32 + m - lane;
            float xv[W], nhv[W + 1];
#pragma unroll
            for (int r = 0; r < W; ++r) xv[r] = xsw[r][kk];
#pragma unroll
            for (int r = 0; r < W + 1; ++r) nhv[r] = hbuf[W * m + r];
            const int e = e0 + m * W;
#pragma unroll
            for (int ph = 0; ph < W; ++ph) {
                int i31 = (e + ph) - (SW - 2);
                bool hok = (i31 >= 1) && (i31 <= N);
                switch (ph) {   // compile-time unrolled: alternates a/b
                    case 0: phase<0,false>(a,b,xw,yv,limR, xv[0], nhv[1], nhv[0], is0, lane, ib+0, hok, pg + 0*PITCH, hq, hdum); break;
                    case 1: phase<1,false>(b,a,xw,yv,limR, xv[1], nhv[2], nhv[1], is0, lane, ib+1, hok, pg + 1*PITCH, hq, hdum); break;
                    case 2: phase<2,false>(a,b,xw,yv,limR, xv[2], nhv[3], nhv[2], is0, lane, ib+2, hok, pg + 2*PITCH, hq, hdum); break;
                    case 3: phase<3,false>(b,a,xw,yv,limR, xv[3], nhv[4], nhv[3], is0, lane, ib+3, hok, pg + 3*PITCH, hq, hdum); break;
                }
                ++hq;
            }
            pg += W * PITCH;
            ib += W;
        }
    }

    // --- persist DP state for the next chunk of this strip ---
#pragma unroll
    for (int q = 0; q < W; ++q) {
        g_state[s][q][lane]     = a[q];
        g_state[s][W + q][lane] = b[q];
    }
}

// ---------------------------------------------------------------------------
// De-skew + sqrt: out[i][j] = sqrt(g_buf[gidx(i+j, j)]).
// ---------------------------------------------------------------------------
constexpr int TR = 128;
constexpr int TC = 32;

__global__ __launch_bounds__(256)
void dtw_deskew(float* __restrict__ out, int N, int M)
{
    __shared__ float sh[TR + TC - 1][TC];
    const int i0 = blockIdx.y * TR;
    const int j0 = blockIdx.x * TC;
    const int d0 = i0 + j0;
    const int pitch_out = M + 1;

    for (int k = threadIdx.x; k < (TR + TC - 1) * TC; k += 256) {
        int dl = k >> 5;
        int jl = k & 31;
        int dg = d0 + dl;
        int jg = j0 + jl;
        float v = 0.0f;
        if (dg <= N + M && jg <= M)
            v = g_buf[gidx(dg, jg)];
        sh[dl][jl] = v;
    }
    __syncthreads();

    for (int k = threadIdx.x; k < TR * TC; k += 256) {
        int ii = k >> 5;
        int jl = k & 31;
        int ig = i0 + ii;
        int jg = j0 + jl;
        if (ig <= N && jg <= M)
            out[(size_t)ig * pitch_out + jg] = sqrtf(sh[ii + jl][jl]);
    }
}

// ---------------------------------------------------------------------------
extern "C" void kernel_launch(void* const* d_in, const int* in_sizes, int n_in,
                              void* d_out, int out_size)
{
    const float* x = (const float*)d_in[0];
    const float* y = (const float*)d_in[1];
    float* out = (float*)d_out;
    const int N = in_sizes[0];
    const int M = in_sizes[1];

    const int nstrips = (M + SW - 1) / SW;              // 48
    const int nchunks = (N + SW + B - 1) / B;           // 49
    const int G = (nchunks - 1) + LAG * (nstrips - 1) + 1;   // 143

    dtw_init<<<64, 256>>>(N, M, nstrips);

    for (int g = 0; g < G; ++g) {
        int s_min = (g - (nchunks - 1) + LAG - 1) / LAG;
        if (s_min < 0) s_min = 0;
        int s_max = g / LAG;
        if (s_max > nstrips - 1) s_max = nstrips - 1;
        if (s_max < s_min) continue;
        dtw_chunk<<<s_max - s_min + 1, 32>>>(x, y, N, M, g, s_min);
    }

    dim3 grid((M + 1 + TC - 1) / TC, (N + 1 + TR - 1) / TR);
    dtw_deskew<<<grid, 256>>>(out, N, M);
}